// round 4
// baseline (speedup 1.0000x reference)
#include <cuda_runtime.h>
#include <cuda_bf16.h>
#include <stdint.h>

#define NN 50000
#define EE 250000
#define FULL 0xffffffffu

// Static scratch
__device__ int    g_cnt[NN];            // degree histogram
__device__ int    g_off[NN + 1];        // CSR offsets (exclusive)
__device__ int    g_cur[NN];            // insertion cursors
__device__ int2   g_csr[EE];            // (src, ea-bits) per edge, dst-bucketed
__device__ float2 g_uvA[NN * 32];       // interleaved (u,v) ping
__device__ float2 g_uvB[NN * 32];       // interleaved (u,v) pong
__device__ float  g_rA[NN * 32];        // root-product ping
__device__ float  g_rB[NN * 32];        // root-product pong

// ---------------- CSR build ----------------
__global__ void hist_kernel(const int* __restrict__ ei, int E) {
    int e = blockIdx.x * blockDim.x + threadIdx.x;
    if (e >= E) return;
    atomicAdd(&g_cnt[ei[E + e]], 1);
}

// single-block exclusive scan over g_cnt -> g_off, g_cur
__global__ void scan_kernel(int N) {
    __shared__ int wsum[32];
    int tid = threadIdx.x, lane = tid & 31, wid = tid >> 5;
    int per = (N + 1023) >> 10;
    int beg = tid * per;
    int endi = min(beg + per, N);
    int sum = 0;
    for (int i = beg; i < endi; i++) sum += g_cnt[i];
    // warp inclusive scan
    int v = sum;
#pragma unroll
    for (int o = 1; o < 32; o <<= 1) {
        int t = __shfl_up_sync(FULL, v, o);
        if (lane >= o) v += t;
    }
    if (lane == 31) wsum[wid] = v;
    __syncthreads();
    if (wid == 0) {
        int w = wsum[lane];
        int wv = w;
#pragma unroll
        for (int o = 1; o < 32; o <<= 1) {
            int t = __shfl_up_sync(FULL, wv, o);
            if (lane >= o) wv += t;
        }
        wsum[lane] = wv - w;   // exclusive warp offsets
    }
    __syncthreads();
    int run = v - sum + wsum[wid];     // global exclusive prefix
    for (int i = beg; i < endi; i++) {
        g_off[i] = run;
        g_cur[i] = run;
        run += g_cnt[i];
    }
    if (tid == 1023) g_off[N] = run;   // == E
}

__global__ void permute_kernel(const int* __restrict__ ei,
                               const float* __restrict__ ea, int E) {
    int e = blockIdx.x * blockDim.x + threadIdx.x;
    if (e >= E) return;
    int dst = ei[E + e];
    int p = atomicAdd(&g_cur[dst], 1);
    g_csr[p] = make_int2(ei[e], __float_as_int(ea[e]));
}

// ---------------- shuffle GEMM helper ----------------
__device__ __forceinline__ void load_weights(float* Ws,
                                             const float* __restrict__ l1W,
                                             const float* __restrict__ l1b,
                                             const float* __restrict__ root) {
    for (int k = threadIdx.x; k < 1024; k += blockDim.x) {
        Ws[k]        = l1W[k];
        Ws[1024 + k] = l1b[k];
        Ws[2048 + k] = root[k];
    }
    __syncthreads();
}

__device__ __forceinline__ void shfl_gemm(float rv, const float* Ws, int lane,
                                          float2* ouv, float* orr) {
    float au = 0.f, av = 0.f, ar = 0.f;
#pragma unroll
    for (int i = 0; i < 32; i++) {
        float b = __shfl_sync(FULL, rv, i);
        au = fmaf(b, Ws[i * 32 + lane], au);
        av = fmaf(b, Ws[1024 + i * 32 + lane], av);
        ar = fmaf(b, Ws[2048 + i * 32 + lane], ar);
    }
    ouv[lane] = make_float2(au, av);
    orr[lane] = ar;
}

// gemm0: (uvA, rA) = relu(x*nW+nb) @ [W1|B1|root]
__global__ void gemm0_kernel(const float* __restrict__ x,
                             const float* __restrict__ nW,
                             const float* __restrict__ nb,
                             const float* __restrict__ l1W,
                             const float* __restrict__ l1b,
                             const float* __restrict__ root, int N) {
    __shared__ float Ws[3 * 1024];
    load_weights(Ws, l1W, l1b, root);
    int warp = threadIdx.x >> 5, lane = threadIdx.x & 31;
    int n = blockIdx.x * (blockDim.x >> 5) + warp;
    if (n >= N) return;
    float h = fmaf(x[n], nW[lane], nb[lane]);
    shfl_gemm(fmaxf(h, 0.f), Ws, lane, &g_uvA[n * 32], &g_rA[n * 32]);
}

// fused layer: gather mean -> combine -> (relu -> gemm | write out)
__global__ void layer_kernel(const float2* __restrict__ uv_in,
                             const float* __restrict__ r_in,
                             float2* __restrict__ uv_out,
                             float* __restrict__ r_out,
                             const float* __restrict__ l1W,
                             const float* __restrict__ l1b,
                             const float* __restrict__ root,
                             const float* __restrict__ convb,
                             float* __restrict__ out,
                             int N, int final_layer) {
    __shared__ float Ws[3 * 1024];
    if (!final_layer) load_weights(Ws, l1W, l1b, root);
    int warp = threadIdx.x >> 5, lane = threadIdx.x & 31;
    int n = blockIdx.x * (blockDim.x >> 5) + warp;
    if (n >= N) return;

    int start = g_off[n], end = g_off[n + 1];
    float au0 = 0.f, av0 = 0.f, au1 = 0.f, av1 = 0.f;
    for (int base = start; base < end; base += 32) {
        int m = min(32, end - base);
        int2 sa = make_int2(0, 0);
        if (lane < m) sa = __ldg(&g_csr[base + lane]);
        int j = 0;
        for (; j + 4 <= m; j += 4) {
            int s0 = __shfl_sync(FULL, sa.x, j);
            int s1 = __shfl_sync(FULL, sa.x, j + 1);
            int s2 = __shfl_sync(FULL, sa.x, j + 2);
            int s3 = __shfl_sync(FULL, sa.x, j + 3);
            float a0 = __int_as_float(__shfl_sync(FULL, sa.y, j));
            float a1 = __int_as_float(__shfl_sync(FULL, sa.y, j + 1));
            float a2 = __int_as_float(__shfl_sync(FULL, sa.y, j + 2));
            float a3 = __int_as_float(__shfl_sync(FULL, sa.y, j + 3));
            float2 t0 = __ldg(&uv_in[s0 * 32 + lane]);
            float2 t1 = __ldg(&uv_in[s1 * 32 + lane]);
            float2 t2 = __ldg(&uv_in[s2 * 32 + lane]);
            float2 t3 = __ldg(&uv_in[s3 * 32 + lane]);
            au0 = fmaf(a0, t0.x, au0); av0 += t0.y;
            au1 = fmaf(a1, t1.x, au1); av1 += t1.y;
            au0 = fmaf(a2, t2.x, au0); av0 += t2.y;
            au1 = fmaf(a3, t3.x, au1); av1 += t3.y;
        }
        for (; j < m; j++) {
            int s0 = __shfl_sync(FULL, sa.x, j);
            float a0 = __int_as_float(__shfl_sync(FULL, sa.y, j));
            float2 t0 = __ldg(&uv_in[s0 * 32 + lane]);
            au0 = fmaf(a0, t0.x, au0); av0 += t0.y;
        }
    }
    float c = fmaxf((float)(end - start), 1.0f);
    float h = (au0 + au1 + av0 + av1) / c + r_in[n * 32 + lane] + convb[lane];

    if (final_layer) { out[n * 32 + lane] = h; return; }
    shfl_gemm(fmaxf(h, 0.f), Ws, lane, &uv_out[n * 32], &r_out[n * 32]);
}

extern "C" void kernel_launch(void* const* d_in, const int* in_sizes, int n_in,
                              void* d_out, int out_size) {
    const float* x     = (const float*)d_in[0];
    const int*   ei    = (const int*)d_in[1];
    const float* ea    = (const float*)d_in[2];
    const float* nW    = (const float*)d_in[5];
    const float* nb    = (const float*)d_in[6];
    const float* l1W   = (const float*)d_in[7];
    const float* l1b   = (const float*)d_in[8];
    const float* root  = (const float*)d_in[9];
    const float* convb = (const float*)d_in[10];

    int N = in_sizes[0];      // 50000
    int E = in_sizes[2];      // 250000
    float* out = (float*)d_out;

    void *p_cnt, *p_uvA, *p_uvB, *p_rA, *p_rB;
    cudaGetSymbolAddress(&p_cnt, g_cnt);
    cudaGetSymbolAddress(&p_uvA, g_uvA);
    cudaGetSymbolAddress(&p_uvB, g_uvB);
    cudaGetSymbolAddress(&p_rA, g_rA);
    cudaGetSymbolAddress(&p_rB, g_rB);
    float2* uvA = (float2*)p_uvA;
    float2* uvB = (float2*)p_uvB;
    float*  rA  = (float*)p_rA;
    float*  rB  = (float*)p_rB;

    cudaMemsetAsync(p_cnt, 0, (size_t)N * sizeof(int));

    int tb = 256;
    int blks_e = (E + tb - 1) / tb;
    int blks_w = (N + (tb / 32) - 1) / (tb / 32);   // warp-per-node

    hist_kernel<<<blks_e, tb>>>(ei, E);
    scan_kernel<<<1, 1024>>>(N);
    permute_kernel<<<blks_e, tb>>>(ei, ea, E);

    gemm0_kernel<<<blks_w, tb>>>(x, nW, nb, l1W, l1b, root, N);
    layer_kernel<<<blks_w, tb>>>(uvA, rA, uvB, rB, l1W, l1b, root, convb, out, N, 0);
    layer_kernel<<<blks_w, tb>>>(uvB, rB, uvA, rA, l1W, l1b, root, convb, out, N, 0);
    layer_kernel<<<blks_w, tb>>>(uvA, rA, uvB, rB, l1W, l1b, root, convb, out, N, 1);
}

// round 5
// speedup vs baseline: 1.2003x; 1.2003x over previous
#include <cuda_runtime.h>
#include <cuda_bf16.h>
#include <stdint.h>

#define NN 50000
#define EE 250000
#define FULL 0xffffffffu

// Static scratch
__device__ int   g_cnt[NN];
__device__ int   g_off[NN + 1];
__device__ int   g_cur[NN];
__device__ int   g_csr_src[EE];
__device__ float g_csr_ea[EE];
__device__ float g_h[NN * 32];       // node features (pre-relu)
__device__ float g_uvr[NN * 96];     // [u | v | r] = relu(h) @ [W1 | B1 | root]

// ---------------- CSR build ----------------
__global__ void hist_kernel(const int* __restrict__ ei, int E) {
    int e = blockIdx.x * blockDim.x + threadIdx.x;
    if (e >= E) return;
    atomicAdd(&g_cnt[ei[E + e]], 1);
}

// single-block exclusive scan over g_cnt -> g_off, g_cur
__global__ void scan_kernel(int N) {
    __shared__ int wsum[32];
    int tid = threadIdx.x, lane = tid & 31, wid = tid >> 5;
    int per = (N + 1023) >> 10;
    int beg = tid * per;
    int endi = min(beg + per, N);
    int sum = 0;
    for (int i = beg; i < endi; i++) sum += g_cnt[i];
    int v = sum;
#pragma unroll
    for (int o = 1; o < 32; o <<= 1) {
        int t = __shfl_up_sync(FULL, v, o);
        if (lane >= o) v += t;
    }
    if (lane == 31) wsum[wid] = v;
    __syncthreads();
    if (wid == 0) {
        int w = wsum[lane];
        int wv = w;
#pragma unroll
        for (int o = 1; o < 32; o <<= 1) {
            int t = __shfl_up_sync(FULL, wv, o);
            if (lane >= o) wv += t;
        }
        wsum[lane] = wv - w;
    }
    __syncthreads();
    int run = v - sum + wsum[wid];
    for (int i = beg; i < endi; i++) {
        g_off[i] = run;
        g_cur[i] = run;
        run += g_cnt[i];
    }
    if (tid == 1023) g_off[N] = run;
}

__global__ void permute_kernel(const int* __restrict__ ei,
                               const float* __restrict__ ea, int E) {
    int e = blockIdx.x * blockDim.x + threadIdx.x;
    if (e >= E) return;
    int dst = ei[E + e];
    int p = atomicAdd(&g_cur[dst], 1);
    g_csr_src[p] = ei[e];
    g_csr_ea[p] = ea[e];
}

// h0[n,d] = x[n]*node_W[d] + node_b[d]
__global__ void init_h_kernel(const float* __restrict__ x,
                              const float* __restrict__ nW,
                              const float* __restrict__ nb, int n_total) {
    int idx = blockIdx.x * blockDim.x + threadIdx.x;
    if (idx >= n_total) return;
    g_h[idx] = fmaf(x[idx >> 5], nW[idx & 31], nb[idx & 31]);
}

// GEMM: uvr[n][0:96] = relu(h[n]) @ [W1 | B1 | root]
// Weights in registers (node-invariant per lane); grid-stride amortizes load.
__global__ void __launch_bounds__(256, 2)
gemm_kernel(const float* __restrict__ hin,
            const float* __restrict__ l1W,
            const float* __restrict__ l1b,
            const float* __restrict__ root, int N) {
    __shared__ float hs[8][33];
    int lane = threadIdx.x & 31, wid = threadIdx.x >> 5;
    float w_u[32], w_v[32], w_r[32];
#pragma unroll
    for (int i = 0; i < 32; i++) {
        w_u[i] = __ldg(&l1W[i * 32 + lane]);
        w_v[i] = __ldg(&l1b[i * 32 + lane]);
        w_r[i] = __ldg(&root[i * 32 + lane]);
    }
    int warp_g = blockIdx.x * 8 + wid;
    int stride = gridDim.x * 8;
    for (int n = warp_g; n < N; n += stride) {
        float hv = fmaxf(__ldg(&hin[n * 32 + lane]), 0.0f);
        hs[wid][lane] = hv;
        __syncwarp();
        float au = 0.f, av = 0.f, ar = 0.f;
#pragma unroll
        for (int i = 0; i < 32; i++) {
            float b = hs[wid][i];
            au = fmaf(b, w_u[i], au);
            av = fmaf(b, w_v[i], av);
            ar = fmaf(b, w_r[i], ar);
        }
        float* o = &g_uvr[n * 96];
        o[lane]      = au;
        o[32 + lane] = av;
        o[64 + lane] = ar;
        __syncwarp();
    }
}

// gather: hout[n] = (sum_e ea*u[src] + v[src]) / max(deg,1) + r[n] + conv_b
__global__ void gather_kernel(const float* __restrict__ convb,
                              float* __restrict__ hout, int N) {
    int warp = threadIdx.x >> 5, lane = threadIdx.x & 31;
    int n = blockIdx.x * (blockDim.x >> 5) + warp;
    if (n >= N) return;
    int start = g_off[n], end = g_off[n + 1];
    float acc = 0.f;
    for (int base = start; base < end; base += 32) {
        int m = min(32, end - base);
        int s = 0; float a = 0.f;
        if (lane < m) { s = g_csr_src[base + lane]; a = g_csr_ea[base + lane]; }
        for (int j = 0; j < m; j++) {
            int   ss = __shfl_sync(FULL, s, j);
            float aa = __shfl_sync(FULL, a, j);
            const float* o = &g_uvr[ss * 96];
            acc = fmaf(aa, __ldg(&o[lane]), acc) + __ldg(&o[32 + lane]);
        }
    }
    float c = fmaxf((float)(end - start), 1.0f);
    hout[n * 32 + lane] = acc / c + g_uvr[n * 96 + 64 + lane] + convb[lane];
}

extern "C" void kernel_launch(void* const* d_in, const int* in_sizes, int n_in,
                              void* d_out, int out_size) {
    const float* x     = (const float*)d_in[0];
    const int*   ei    = (const int*)d_in[1];
    const float* ea    = (const float*)d_in[2];
    const float* nW    = (const float*)d_in[5];
    const float* nb    = (const float*)d_in[6];
    const float* l1W   = (const float*)d_in[7];
    const float* l1b   = (const float*)d_in[8];
    const float* root  = (const float*)d_in[9];
    const float* convb = (const float*)d_in[10];

    int N = in_sizes[0];      // 50000
    int E = in_sizes[2];      // 250000
    float* out = (float*)d_out;

    void *p_cnt, *p_h;
    cudaGetSymbolAddress(&p_cnt, g_cnt);
    cudaGetSymbolAddress(&p_h, g_h);
    float* hbuf = (float*)p_h;

    cudaMemsetAsync(p_cnt, 0, (size_t)N * sizeof(int));

    int tb = 256;
    int blks_e = (E + tb - 1) / tb;
    int blks_w = (N + (tb / 32) - 1) / (tb / 32);   // warp-per-node
    int blks_i = (N * 32 + tb - 1) / tb;

    hist_kernel<<<blks_e, tb>>>(ei, E);
    scan_kernel<<<1, 1024>>>(N);
    permute_kernel<<<blks_e, tb>>>(ei, ea, E);
    init_h_kernel<<<blks_i, tb>>>(x, nW, nb, N * 32);

    // 3 layers (i = 2 -> 3 layers): gemm (relu+transform) then gather (mean+combine)
    gemm_kernel<<<592, tb>>>(hbuf, l1W, l1b, root, N);
    gather_kernel<<<blks_w, tb>>>(convb, hbuf, N);
    gemm_kernel<<<592, tb>>>(hbuf, l1W, l1b, root, N);
    gather_kernel<<<blks_w, tb>>>(convb, hbuf, N);
    gemm_kernel<<<592, tb>>>(hbuf, l1W, l1b, root, N);
    gather_kernel<<<blks_w, tb>>>(convb, out, N);
}